// round 7
// baseline (speedup 1.0000x reference)
#include <cuda_runtime.h>
#include <cfloat>

#define OUTD 5
#define NVOX 125          // OUTD^3
#define NB 2
#define NP 8192
#define NR 64
#define NC 64
#define NT 1024           // threads per CTA
#define PPT (NP / NT)     // 8 points per thread
#define LCAP 1024         // inside-point list capacity (expected ~42)
#define GRID (NB * NR)    // 128 CTAs  (<= 148 SMs -> all co-resident)

// transposed feature scratch [B][P][C], 4 MB
__device__ float g_tf[NB * NP * NC];
// grid barrier ticket counter; zero-init at load, monotonic across graph replays
__device__ unsigned g_bar;

// float atomic max on shared memory via int punning
__device__ __forceinline__ void atomicMaxFloat(float* addr, float value) {
    if (value >= 0.0f) {
        atomicMax((int*)addr, __float_as_int(value));
    } else {
        atomicMin((unsigned int*)addr, __float_as_uint(value));
    }
}

__global__ void __launch_bounds__(NT)
roipool3d_fused(const float* __restrict__ pts,    // [B,P,3]
                const float* __restrict__ feats,  // [B,C,P]
                const float* __restrict__ rois,   // [B,R,7]
                float* __restrict__ out)          // [B*R, C, NVOX]
{
    __shared__ float smax[NC * NVOX];     // [ch][vox] 32000 B (matches out layout)
    __shared__ int   slist[LCAP];         // packed (vid<<13)|p   4096 B
    __shared__ int   scnt;
    __shared__ float tile[2][32 * 33];    // 2 transpose tiles    8448 B -> total 44.5 KB

    const int br  = blockIdx.x;           // 0 .. B*R-1
    const int b   = br / NR;
    const int tid = threadIdx.x;

    // ---- ROI params (uniform across CTA) ----
    const float* roi = rois + br * 7;
    const float cx = roi[0];
    const float cy = roi[1];
    const float dz = roi[5];
    const float cz = roi[2] + 0.5f * dz;       // geometric z center
    const float dx = roi[3];
    const float dy = roi[4];
    const float ry = roi[6];
    const float cosr = cosf(ry), sinr = sinf(ry);
    const float hx = 0.5f * dx, hy = 0.5f * dy, hz = 0.5f * dz;
    const float vx = __fdiv_rn(dx, (float)OUTD);
    const float vy = __fdiv_rn(dy, (float)OUTD);
    const float vz = __fdiv_rn(dz, (float)OUTD);

    // ---- init smax / scnt ----
    {
        float4* s4 = (float4*)smax;
        const float4 neg = make_float4(-FLT_MAX, -FLT_MAX, -FLT_MAX, -FLT_MAX);
        #pragma unroll
        for (int i = tid; i < NC * NVOX / 4; i += NT) s4[i] = neg;
        if (tid == 0) scnt = 0;
    }

    // ---- cooperative transpose: this CTA does tiles g = br + 128k, k=0..7 ----
    // feats [B,C,P] -> g_tf [B,P,C]; 1024 tiles of 32x32 total across the grid.
    {
        const int grp = tid >> 9;          // 0..1 : which of 2 concurrent tiles
        const int t   = tid & 511;
        const int ttx = t & 31;
        const int tty = t >> 5;            // 0..15
        #pragma unroll
        for (int r = 0; r < 4; r++) {
            const int k  = r * 2 + grp;            // 0..7
            const int g  = br + (k << 7);          // tile id 0..1023
            const int tb = g >> 9;                 // batch
            const int c0 = ((g >> 8) & 1) << 5;    // channel block
            const int p0 = (g & 255) << 5;         // point block
            const float* src = feats + ((size_t)(tb * NC + c0)) * NP + p0;
            tile[grp][tty * 33 + ttx]        = src[(size_t)tty * NP + ttx];
            tile[grp][(tty + 16) * 33 + ttx] = src[(size_t)(tty + 16) * NP + ttx];
            __syncthreads();
            float* dst = g_tf + ((size_t)(tb * NP + p0)) * NC + c0;
            dst[(size_t)tty * NC + ttx]        = tile[grp][ttx * 33 + tty];
            dst[(size_t)(tty + 16) * NC + ttx] = tile[grp][ttx * 33 + (tty + 16)];
            __syncthreads();
        }
    }

    const float* ptsb = pts + (size_t)b * NP * 3;

    // ---- hoisted point loads: 24 independent LDGs, latency exposed once ----
    float px[PPT], py[PPT], pz[PPT];
    #pragma unroll
    for (int k = 0; k < PPT; k++) {
        const int p = k * NT + tid;
        px[k] = ptsb[p * 3 + 0];
        py[k] = ptsb[p * 3 + 1];
        pz[k] = ptsb[p * 3 + 2];
    }

    // ---- classify all points, push inside ones to the list ----
    #pragma unroll
    for (int k = 0; k < PPT; k++) {
        const int p = k * NT + tid;
        const float sx = px[k] - cx;
        const float sy = py[k] - cy;
        const float lz = pz[k] - cz;
        const float lx =  sx * cosr + sy * sinr;   // rotate world -> box (-ry)
        const float ly = -sx * sinr + sy * cosr;

        if (fabsf(lx) < hx && fabsf(ly) < hy && fabsf(lz) < hz) {
            int ix = (int)floorf(__fdiv_rn(lx + hx, vx));
            int iy = (int)floorf(__fdiv_rn(ly + hy, vy));
            int iz = (int)floorf(__fdiv_rn(lz + hz, vz));
            ix = min(max(ix, 0), OUTD - 1);
            iy = min(max(iy, 0), OUTD - 1);
            iz = min(max(iz, 0), OUTD - 1);
            const int vid = (ix * OUTD + iy) * OUTD + iz;
            const int slot = atomicAdd(&scnt, 1);
            if (slot < LCAP) slist[slot] = (vid << 13) | p;
        }
    }

    // ---- grid barrier: wait until ALL CTAs finished their transpose tiles ----
    // All 128 CTAs are co-resident (grid <= #SMs, 1 CTA/SM), so spinning is safe.
    // Monotonic ticket counter survives graph replays without reset.
    __syncthreads();                  // CTA done with transpose stores + classify
    if (tid == 0) {
        __threadfence();              // make our g_tf writes visible (release)
        const unsigned t = atomicAdd(&g_bar, 1);
        const unsigned target = ((t >> 7) + 1) << 7;   // this launch's completion count
        volatile unsigned* vb = &g_bar;
        while ((int)(*vb - target) < 0) { }
        __threadfence();              // acquire
    }
    __syncthreads();

    // ---- cooperative gather from g_tf: one float4 (=4 channels) per job ----
    const int n = min(scnt, LCAP);
    const float4* tf4 = (const float4*)(g_tf + (size_t)b * NP * NC);
    for (int i = tid; i < n * 16; i += NT) {
        const int pair = slist[i >> 4];
        const int q    = i & 15;
        const int pp   = pair & (NP - 1);
        const int vid  = pair >> 13;
        const float4 v = __ldg(tf4 + (size_t)pp * 16 + q);
        const int c0   = q * 4;
        atomicMaxFloat(&smax[(c0 + 0) * NVOX + vid], v.x);
        atomicMaxFloat(&smax[(c0 + 1) * NVOX + vid], v.y);
        atomicMaxFloat(&smax[(c0 + 2) * NVOX + vid], v.z);
        atomicMaxFloat(&smax[(c0 + 3) * NVOX + vid], v.w);
    }
    __syncthreads();

    // ---- vectorized write out [C, NVOX]; empty voxel (still -FLT_MAX) -> 0 ----
    float4*       o4 = (float4*)(out + (size_t)br * NC * NVOX);
    const float4* s4 = (const float4*)smax;
    #pragma unroll
    for (int i = tid; i < NC * NVOX / 4; i += NT) {
        float4 m = s4[i];
        m.x = (m.x == -FLT_MAX) ? 0.0f : m.x;
        m.y = (m.y == -FLT_MAX) ? 0.0f : m.y;
        m.z = (m.z == -FLT_MAX) ? 0.0f : m.z;
        m.w = (m.w == -FLT_MAX) ? 0.0f : m.w;
        o4[i] = m;
    }
}

extern "C" void kernel_launch(void* const* d_in, const int* in_sizes, int n_in,
                              void* d_out, int out_size) {
    const float* pts   = (const float*)d_in[0];  // points_xyz [B,P,3]
    const float* feats = (const float*)d_in[1];  // features   [B,C,P]
    const float* rois  = (const float*)d_in[2];  // rois       [B,R,7]
    float* out = (float*)d_out;                  // [B*R, C, NVOX]
    roipool3d_fused<<<GRID, NT>>>(pts, feats, rois, out);
}

// round 8
// speedup vs baseline: 1.2866x; 1.2866x over previous
#include <cuda_runtime.h>
#include <cfloat>

#define OUTD 5
#define NVOX 125          // OUTD^3
#define NB 2
#define NP 8192
#define NR 64
#define NC 64
#define NT 1024           // threads per CTA
#define PPT (NP / NT)     // 8 points per thread
#define LCAP 1024         // inside-point list capacity (expected ~42)
#define GRID (NB * NR)

// dynamic smem layout (floats): smax[8000] | pbuf[24576] | slist[1024] | scnt
#define SMAX_F   (NC * NVOX)          // 8000 floats
#define PBUF_F   (NP * 3)             // 24576 floats
#define SMEM_BYTES ((SMAX_F + PBUF_F) * 4 + LCAP * 4 + 16)

// float atomic max on shared memory via int punning
__device__ __forceinline__ void atomicMaxFloat(float* addr, float value) {
    if (value >= 0.0f) {
        atomicMax((int*)addr, __float_as_int(value));
    } else {
        atomicMin((unsigned int*)addr, __float_as_uint(value));
    }
}

__global__ void __launch_bounds__(NT)
roipool3d_kernel(const float* __restrict__ pts,    // [B,P,3]
                 const float* __restrict__ feats,  // [B,C,P]
                 const float* __restrict__ rois,   // [B,R,7]
                 float* __restrict__ out)          // [B*R, C, NVOX]
{
    extern __shared__ float dyn[];
    float* smax  = dyn;                         // [ch][vox], matches out layout
    float* pbuf  = dyn + SMAX_F;                // point slab [P][3]
    int*   slist = (int*)(dyn + SMAX_F + PBUF_F);
    int*   scnt  = slist + LCAP;

    const int br   = blockIdx.x;                // 0 .. B*R-1
    const int b    = br / NR;
    const int tid  = threadIdx.x;
    const int lane = tid & 31;

    // ---- ROI params (uniform across CTA) ----
    const float* roi = rois + br * 7;
    const float cx = roi[0];
    const float cy = roi[1];
    const float dz = roi[5];
    const float cz = roi[2] + 0.5f * dz;        // geometric z center
    const float dx = roi[3];
    const float dy = roi[4];
    const float ry = roi[6];
    const float cosr = cosf(ry), sinr = sinf(ry);
    const float hx = 0.5f * dx, hy = 0.5f * dy, hz = 0.5f * dz;
    const float vx = __fdiv_rn(dx, (float)OUTD);
    const float vy = __fdiv_rn(dy, (float)OUTD);
    const float vz = __fdiv_rn(dz, (float)OUTD);

    // ---- coalesced slab load: whole batch's points -> smem (6 LDG.128/thread) ----
    {
        const float4* src4 = (const float4*)(pts + (size_t)b * NP * 3);
        float4*       dst4 = (float4*)pbuf;
        #pragma unroll
        for (int k = 0; k < PBUF_F / 4 / NT; k++)       // 6
            dst4[k * NT + tid] = src4[k * NT + tid];
    }

    // ---- init smax / scnt (overlaps slab-load latency) ----
    {
        float4* s4 = (float4*)smax;
        const float4 neg = make_float4(-FLT_MAX, -FLT_MAX, -FLT_MAX, -FLT_MAX);
        #pragma unroll
        for (int i = tid; i < SMAX_F / 4; i += NT) s4[i] = neg;
        if (tid == 0) *scnt = 0;
    }
    __syncthreads();

    // ---- classify from smem (conflict-free: stride 3 coprime to 32 banks) ----
    #pragma unroll
    for (int k = 0; k < PPT; k++) {
        const int p = k * NT + tid;
        const float sx = pbuf[p * 3 + 0] - cx;
        const float sy = pbuf[p * 3 + 1] - cy;
        const float lz = pbuf[p * 3 + 2] - cz;
        const float lx =  sx * cosr + sy * sinr;   // rotate world -> box (-ry)
        const float ly = -sx * sinr + sy * cosr;

        const bool inside = (fabsf(lx) < hx) && (fabsf(ly) < hy) && (fabsf(lz) < hz);
        int vid = 0;
        if (inside) {
            int ix = (int)floorf(__fdiv_rn(lx + hx, vx));
            int iy = (int)floorf(__fdiv_rn(ly + hy, vy));
            int iz = (int)floorf(__fdiv_rn(lz + hz, vz));
            ix = min(max(ix, 0), OUTD - 1);
            iy = min(max(iy, 0), OUTD - 1);
            iz = min(max(iz, 0), OUTD - 1);
            vid = (ix * OUTD + iy) * OUTD + iz;
        }
        // warp-aggregated list push: one atomic per warp
        const unsigned m = __ballot_sync(0xffffffffu, inside);
        if (m) {
            const int leader = __ffs(m) - 1;
            int basew = 0;
            if (lane == leader) basew = atomicAdd(scnt, __popc(m));
            basew = __shfl_sync(0xffffffffu, basew, leader);
            if (inside) {
                const int slot = basew + __popc(m & ((1u << lane) - 1u));
                if (slot < LCAP) slist[slot] = (vid << 13) | p;
            }
        }
    }
    __syncthreads();

    // ---- cooperative gather: (pair, channel) jobs, batch-4 loads for MLP ----
    const int n     = min(*scnt, LCAP);
    const int total = n * NC;
    const float* featb = feats + (size_t)b * NC * NP;
    for (int base = 0; base < total; base += NT * 4) {
        float v[4];
        int   dstoff[4];
        bool  act[4];
        #pragma unroll
        for (int j = 0; j < 4; j++) {
            const int i = base + j * NT + tid;
            act[j] = (i < total);
            v[j] = 0.0f; dstoff[j] = 0;
            if (act[j]) {
                const int pair = slist[i >> 6];
                const int c    = i & (NC - 1);
                const int pp   = pair & (NP - 1);
                const int vid  = pair >> 13;
                v[j]      = __ldg(featb + (size_t)c * NP + pp);
                dstoff[j] = c * NVOX + vid;        // stride 125: conflict-free
            }
        }
        #pragma unroll
        for (int j = 0; j < 4; j++)
            if (act[j]) atomicMaxFloat(&smax[dstoff[j]], v[j]);
    }
    __syncthreads();

    // ---- vectorized write out [C, NVOX]; empty voxel (still -FLT_MAX) -> 0 ----
    float4*       o4 = (float4*)(out + (size_t)br * NC * NVOX);
    const float4* s4 = (const float4*)smax;
    #pragma unroll
    for (int i = tid; i < SMAX_F / 4; i += NT) {
        float4 m = s4[i];
        m.x = (m.x == -FLT_MAX) ? 0.0f : m.x;
        m.y = (m.y == -FLT_MAX) ? 0.0f : m.y;
        m.z = (m.z == -FLT_MAX) ? 0.0f : m.z;
        m.w = (m.w == -FLT_MAX) ? 0.0f : m.w;
        o4[i] = m;
    }
}

extern "C" void kernel_launch(void* const* d_in, const int* in_sizes, int n_in,
                              void* d_out, int out_size) {
    const float* pts   = (const float*)d_in[0];  // points_xyz [B,P,3]
    const float* feats = (const float*)d_in[1];  // features   [B,C,P]
    const float* rois  = (const float*)d_in[2];  // rois       [B,R,7]
    float* out = (float*)d_out;                  // [B*R, C, NVOX]

    static bool attr_set = false;                // host-side only; idempotent
    if (!attr_set) {
        cudaFuncSetAttribute(roipool3d_kernel,
                             cudaFuncAttributeMaxDynamicSharedMemorySize,
                             SMEM_BYTES);
        attr_set = true;
    }
    roipool3d_kernel<<<GRID, NT, SMEM_BYTES>>>(pts, feats, rois, out);
}